// round 1
// baseline (speedup 1.0000x reference)
#include <cuda_runtime.h>
#include <math.h>

#define BATCH 16
#define C3C 512
#define C4C 1024
#define CIN 1536
#define COUT 512
#define HH 64
#define WW 64
#define HW 4096
#define H4 32
#define NROI 10

// Scratch (static device arrays — allocation-guard safe)
__device__ float g_c4u[(size_t)BATCH * C4C * HW];   // 268 MB upsampled c4
__device__ float g_attr[(size_t)BATCH * COUT * HW]; // 134 MB conv+bn+relu output

// ---------------------------------------------------------------------------
// Kernel 1: bilinear 2x upsample (half-pixel, edge-clamped) c4 -> g_c4u
// ---------------------------------------------------------------------------
__global__ void __launch_bounds__(256) upsample_kernel(const float* __restrict__ c4) {
    size_t idx = (size_t)blockIdx.x * blockDim.x + threadIdx.x; // BATCH*C4C*HW exact
    int w = (int)(idx & 63);
    int h = (int)((idx >> 6) & 63);
    size_t bc = idx >> 12;
    const float* __restrict__ src = c4 + bc * (H4 * H4);

    float fy = h * 0.5f - 0.25f;
    int h0 = (int)floorf(fy);
    float ty = fy - (float)h0;
    int h1 = min(h0 + 1, H4 - 1);
    h0 = max(h0, 0);

    float fx = w * 0.5f - 0.25f;
    int w0 = (int)floorf(fx);
    float tx = fx - (float)w0;
    int w1 = min(w0 + 1, H4 - 1);
    w0 = max(w0, 0);

    float v00 = src[h0 * H4 + w0];
    float v01 = src[h0 * H4 + w1];
    float v10 = src[h1 * H4 + w0];
    float v11 = src[h1 * H4 + w1];
    float v = (1.f - ty) * ((1.f - tx) * v00 + tx * v01)
            +        ty  * ((1.f - tx) * v10 + tx * v11);
    g_c4u[idx] = v;
}

// ---------------------------------------------------------------------------
// Kernel 2: batched GEMM  attr[b] = ReLU(BN(W @ concat(c3[b], c4u[b]) + b_conv))
// M=512 (out ch), K=1536 (in ch), N=4096 (pixels), per-batch.
// 128x128x8 tile, 8x8 per-thread register tile, 256 threads.
// ---------------------------------------------------------------------------
__global__ void __launch_bounds__(256) gemm_bn_relu_kernel(
    const float* __restrict__ c3, const float* __restrict__ Wc,
    const float* __restrict__ bconv, const float* __restrict__ gamma,
    const float* __restrict__ beta, const float* __restrict__ mean,
    const float* __restrict__ var)
{
    __shared__ float As[8][128];
    __shared__ float Bs[8][128];

    const int b = blockIdx.z;
    const int mBase = blockIdx.y * 128;
    const int nBase = blockIdx.x * 128;
    const int tid = threadIdx.x;

    const int aRow = tid >> 1;          // 0..127
    const int aK   = (tid & 1) * 4;     // 0 or 4
    const int bRow = tid >> 5;          // 0..7
    const int bCol = (tid & 31) * 4;    // 0..124

    const int tx = tid & 15;            // col group
    const int ty = tid >> 4;            // row group

    const float* __restrict__ c3b = c3 + (size_t)b * C3C * HW;
    const float* __restrict__ c4b = g_c4u + (size_t)b * C4C * HW;

    float acc[8][8];
#pragma unroll
    for (int i = 0; i < 8; i++)
#pragma unroll
        for (int j = 0; j < 8; j++) acc[i][j] = 0.f;

    for (int k0 = 0; k0 < CIN; k0 += 8) {
        // load A tile (W is [COUT, CIN] row-major)
        float4 a4 = *(const float4*)(Wc + (size_t)(mBase + aRow) * CIN + k0 + aK);
        As[aK + 0][aRow] = a4.x;
        As[aK + 1][aRow] = a4.y;
        As[aK + 2][aRow] = a4.z;
        As[aK + 3][aRow] = a4.w;

        // load B tile from the virtual concat(c3, c4u)
        int c = k0 + bRow;
        const float* srow = (c < C3C) ? (c3b + (size_t)c * HW)
                                      : (c4b + (size_t)(c - C3C) * HW);
        *(float4*)&Bs[bRow][bCol] = *(const float4*)(srow + nBase + bCol);

        __syncthreads();

#pragma unroll
        for (int kk = 0; kk < 8; kk++) {
            float ra[8], rb[8];
#pragma unroll
            for (int i = 0; i < 8; i++) ra[i] = As[kk][ty * 8 + i];
#pragma unroll
            for (int j = 0; j < 8; j++) rb[j] = Bs[kk][tx * 8 + j];
#pragma unroll
            for (int i = 0; i < 8; i++)
#pragma unroll
                for (int j = 0; j < 8; j++)
                    acc[i][j] += ra[i] * rb[j];
        }
        __syncthreads();
    }

    // epilogue: bias + BN (eval) + ReLU
#pragma unroll
    for (int i = 0; i < 8; i++) {
        int o = mBase + ty * 8 + i;
        float inv = gamma[o] * rsqrtf(var[o] + 1e-5f);
        float sh  = beta[o] + (bconv[o] - mean[o]) * inv;
        float* orow = g_attr + ((size_t)b * COUT + o) * HW + nBase + tx * 8;
        float4 r0, r1;
        r0.x = fmaxf(acc[i][0] * inv + sh, 0.f);
        r0.y = fmaxf(acc[i][1] * inv + sh, 0.f);
        r0.z = fmaxf(acc[i][2] * inv + sh, 0.f);
        r0.w = fmaxf(acc[i][3] * inv + sh, 0.f);
        r1.x = fmaxf(acc[i][4] * inv + sh, 0.f);
        r1.y = fmaxf(acc[i][5] * inv + sh, 0.f);
        r1.z = fmaxf(acc[i][6] * inv + sh, 0.f);
        r1.w = fmaxf(acc[i][7] * inv + sh, 0.f);
        *(float4*)orow = r0;
        *(float4*)(orow + 4) = r1;
    }
}

// ---------------------------------------------------------------------------
// Kernel 3: copy boxes passthrough to output head
// ---------------------------------------------------------------------------
__global__ void copy_boxes_kernel(const float* __restrict__ boxes, float* __restrict__ out) {
    int i = blockIdx.x * blockDim.x + threadIdx.x;
    if (i < BATCH * NROI * 4) out[i] = boxes[i];
}

// ---------------------------------------------------------------------------
// Kernel 4: ROI adaptive-avg-pool 5x5. One block per (batch, roi).
// 8 warps; each warp handles channels c = warp, warp+8, ... Lane p*5+q
// computes one output bin.
// ---------------------------------------------------------------------------
__global__ void __launch_bounds__(256) roi_pool_kernel(const float* __restrict__ boxes,
                                                       float* __restrict__ out)
{
    const int br = blockIdx.x;           // 0..159
    const int b = br / NROI;
    const float* box = boxes + (size_t)br * 4;

    const float sx = (float)WW / 512.0f; // 0.125
    const float sy = (float)HH / 512.0f;

    int x1 = min(max((int)floorf(box[0] * sx), 0), WW - 1);
    int y1 = min(max((int)floorf(box[1] * sy), 0), HH - 1);
    int x2 = min(max((int)ceilf(box[2] * sx), 0), WW - 1);
    int y2 = min(max((int)ceilf(box[3] * sy), 0), HH - 1);
    if (x2 <= x1) x2 = min(x1 + 1, WW);
    if (y2 <= y1) y2 = min(y1 + 1, HH);
    const int Lx = x2 - x1;
    const int Ly = y2 - y1;

    const int warp = threadIdx.x >> 5;
    const int lane = threadIdx.x & 31;

    int hs = 0, he = 0, ws = 0, we = 0;
    float invArea = 0.f;
    if (lane < 25) {
        int p = lane / 5, q = lane % 5;
        hs = y1 + (p * Ly) / 5;
        he = y1 + ((p + 1) * Ly + 4) / 5;
        ws = x1 + (q * Lx) / 5;
        we = x1 + ((q + 1) * Lx + 4) / 5;
        invArea = 1.0f / (float)((he - hs) * (we - ws));
    }

    const float* attrB = g_attr + (size_t)b * COUT * HW;
    float* outBR = out + (size_t)BATCH * NROI * 4 + (size_t)br * COUT * 25;

    for (int c = warp; c < COUT; c += 8) {
        if (lane < 25) {
            const float* plane = attrB + (size_t)c * HW;
            float s = 0.f;
            for (int h = hs; h < he; h++) {
                const float* row = plane + h * WW;
                for (int w = ws; w < we; w++) s += row[w];
            }
            outBR[(size_t)c * 25 + lane] = s * invArea;
        }
    }
}

// ---------------------------------------------------------------------------
extern "C" void kernel_launch(void* const* d_in, const int* in_sizes, int n_in,
                              void* d_out, int out_size)
{
    const float* c3    = (const float*)d_in[0];
    const float* c4    = (const float*)d_in[1];
    const float* boxes = (const float*)d_in[2];
    const float* wconv = (const float*)d_in[3];
    const float* bconv = (const float*)d_in[4];
    const float* gamma = (const float*)d_in[5];
    const float* beta  = (const float*)d_in[6];
    const float* mean  = (const float*)d_in[7];
    const float* var   = (const float*)d_in[8];
    float* out = (float*)d_out;

    // 1) upsample c4 -> g_c4u  (16*1024*4096 = 67,108,864 elems, exact multiple of 256)
    upsample_kernel<<<262144, 256>>>(c4);

    // 2) batched GEMM + BN + ReLU -> g_attr
    gemm_bn_relu_kernel<<<dim3(HW / 128, COUT / 128, BATCH), 256>>>(
        c3, wconv, bconv, gamma, beta, mean, var);

    // 3) boxes passthrough
    copy_boxes_kernel<<<3, 256>>>(boxes, out);

    // 4) ROI pooling
    roi_pool_kernel<<<BATCH * NROI, 256>>>(boxes, out);
}

// round 4
// speedup vs baseline: 2.7608x; 2.7608x over previous
#include <cuda_runtime.h>
#include <math.h>

#define BATCH 16
#define C3C 512
#define C4C 1024
#define CIN 1536
#define COUT 512
#define HH 64
#define WW 64
#define HW 4096
#define H4 32
#define NROI 10

#define BM 128
#define BN 128
#define BK 16
#define SMP 136   // padded smem row stride (floats): bank-conflict-free frag loads

// Scratch (static device arrays — allocation-guard safe)
__device__ float g_c4u[(size_t)BATCH * C4C * HW];   // 268 MB upsampled c4
__device__ float g_attr[(size_t)BATCH * COUT * HW]; // 134 MB conv+bn+relu output

__device__ __forceinline__ float f2tf32(float x) {
    unsigned u;
    asm("cvt.rna.tf32.f32 %0, %1;" : "=r"(u) : "f"(x));
    return __uint_as_float(u);
}

// ---------------------------------------------------------------------------
// Kernel 1: bilinear 2x upsample (half-pixel, edge-clamped) c4 -> g_c4u
// ---------------------------------------------------------------------------
__global__ void __launch_bounds__(256) upsample_kernel(const float* __restrict__ c4) {
    size_t idx = (size_t)blockIdx.x * blockDim.x + threadIdx.x;
    int w = (int)(idx & 63);
    int h = (int)((idx >> 6) & 63);
    size_t bc = idx >> 12;
    const float* __restrict__ src = c4 + bc * (H4 * H4);

    float fy = h * 0.5f - 0.25f;
    int h0 = (int)floorf(fy);
    float ty = fy - (float)h0;
    int h1 = min(h0 + 1, H4 - 1);
    h0 = max(h0, 0);

    float fx = w * 0.5f - 0.25f;
    int w0 = (int)floorf(fx);
    float tx = fx - (float)w0;
    int w1 = min(w0 + 1, H4 - 1);
    w0 = max(w0, 0);

    float v00 = src[h0 * H4 + w0];
    float v01 = src[h0 * H4 + w1];
    float v10 = src[h1 * H4 + w0];
    float v11 = src[h1 * H4 + w1];
    float v = (1.f - ty) * ((1.f - tx) * v00 + tx * v01)
            +        ty  * ((1.f - tx) * v10 + tx * v11);
    g_c4u[idx] = v;
}

// ---------------------------------------------------------------------------
// Kernel 2: batched GEMM (tf32 mma.sync)  attr = ReLU(BN(W @ concat + b))
// M=512, K=1536, N=4096 per batch. 128x128x16 tile, 8 warps of 64x32.
// ---------------------------------------------------------------------------
__global__ void __launch_bounds__(256, 2) gemm_bn_relu_kernel(
    const float* __restrict__ c3, const float* __restrict__ Wc,
    const float* __restrict__ bconv, const float* __restrict__ gamma,
    const float* __restrict__ beta, const float* __restrict__ mean,
    const float* __restrict__ var)
{
    __shared__ float As[BK * SMP];  // [k][m], padded
    __shared__ float Bs[BK * SMP];  // [k][n], padded

    const int b = blockIdx.z;
    const int mBase = blockIdx.y * BM;
    const int nBase = blockIdx.x * BN;
    const int tid = threadIdx.x;
    const int lane = tid & 31;
    const int warpId = tid >> 5;
    const int warpM = warpId & 1;   // 0..1 -> 64 rows each
    const int warpN = warpId >> 1;  // 0..3 -> 32 cols each
    const int lane4 = lane & 3;
    const int laneq = lane >> 2;

    const float* __restrict__ c3b = c3 + (size_t)b * C3C * HW;
    const float* __restrict__ c4b = g_c4u + (size_t)b * C4C * HW;

    // A-load mapping: row = tid>>1 (0..127), kh = (tid&1)*8
    const int aRow = tid >> 1;
    const int aKh = (tid & 1) * 8;
    // B-load mapping: r = tid>>4 (0..15), c = (tid&15)*8
    const int bRow = tid >> 4;
    const int bCol = (tid & 15) * 8;

    float acc[4][4][4];
#pragma unroll
    for (int i = 0; i < 4; i++)
#pragma unroll
        for (int j = 0; j < 4; j++)
#pragma unroll
            for (int r = 0; r < 4; r++) acc[i][j][r] = 0.f;

    for (int k0 = 0; k0 < CIN; k0 += BK) {
        // --- load A tile: W[mBase+aRow][k0+aKh .. +8], store transposed tf32
        {
            const float* wp = Wc + (size_t)(mBase + aRow) * CIN + k0 + aKh;
            float4 a0 = *(const float4*)wp;
            float4 a1 = *(const float4*)(wp + 4);
            As[(aKh + 0) * SMP + aRow] = f2tf32(a0.x);
            As[(aKh + 1) * SMP + aRow] = f2tf32(a0.y);
            As[(aKh + 2) * SMP + aRow] = f2tf32(a0.z);
            As[(aKh + 3) * SMP + aRow] = f2tf32(a0.w);
            As[(aKh + 4) * SMP + aRow] = f2tf32(a1.x);
            As[(aKh + 5) * SMP + aRow] = f2tf32(a1.y);
            As[(aKh + 6) * SMP + aRow] = f2tf32(a1.z);
            As[(aKh + 7) * SMP + aRow] = f2tf32(a1.w);
        }
        // --- load B tile from virtual concat(c3,c4u), tf32-rounded
        {
            int c = k0 + bRow;
            const float* srow = (c < C3C) ? (c3b + (size_t)c * HW)
                                          : (c4b + (size_t)(c - C3C) * HW);
            float4 v0 = *(const float4*)(srow + nBase + bCol);
            float4 v1 = *(const float4*)(srow + nBase + bCol + 4);
            float4 t0, t1;
            t0.x = f2tf32(v0.x); t0.y = f2tf32(v0.y); t0.z = f2tf32(v0.z); t0.w = f2tf32(v0.w);
            t1.x = f2tf32(v1.x); t1.y = f2tf32(v1.y); t1.z = f2tf32(v1.z); t1.w = f2tf32(v1.w);
            *(float4*)&Bs[bRow * SMP + bCol] = t0;
            *(float4*)&Bs[bRow * SMP + bCol + 4] = t1;
        }
        __syncthreads();

#pragma unroll
        for (int ks = 0; ks < BK; ks += 8) {
            // load A frags: 4 frags of m16k8
            unsigned af[4][4];
#pragma unroll
            for (int i = 0; i < 4; i++) {
                int m0 = warpM * 64 + i * 16 + laneq;
                af[i][0] = __float_as_uint(As[(ks + lane4) * SMP + m0]);
                af[i][1] = __float_as_uint(As[(ks + lane4) * SMP + m0 + 8]);
                af[i][2] = __float_as_uint(As[(ks + lane4 + 4) * SMP + m0]);
                af[i][3] = __float_as_uint(As[(ks + lane4 + 4) * SMP + m0 + 8]);
            }
            // load B frags: 4 frags of k8n8
            unsigned bf[4][2];
#pragma unroll
            for (int j = 0; j < 4; j++) {
                int n0 = warpN * 32 + j * 8 + laneq;
                bf[j][0] = __float_as_uint(Bs[(ks + lane4) * SMP + n0]);
                bf[j][1] = __float_as_uint(Bs[(ks + lane4 + 4) * SMP + n0]);
            }
#pragma unroll
            for (int i = 0; i < 4; i++)
#pragma unroll
                for (int j = 0; j < 4; j++) {
                    asm volatile(
                        "mma.sync.aligned.m16n8k8.row.col.f32.tf32.tf32.f32 "
                        "{%0,%1,%2,%3}, {%4,%5,%6,%7}, {%8,%9}, {%0,%1,%2,%3};\n"
                        : "+f"(acc[i][j][0]), "+f"(acc[i][j][1]),
                          "+f"(acc[i][j][2]), "+f"(acc[i][j][3])
                        : "r"(af[i][0]), "r"(af[i][1]), "r"(af[i][2]), "r"(af[i][3]),
                          "r"(bf[j][0]), "r"(bf[j][1]));
                }
        }
        __syncthreads();
    }

    // epilogue: bias + BN + ReLU -> g_attr
#pragma unroll
    for (int i = 0; i < 4; i++) {
        int r0 = mBase + warpM * 64 + i * 16 + laneq;     // row of c0/c1
        int r1 = r0 + 8;                                  // row of c2/c3
        float inv0 = gamma[r0] * rsqrtf(var[r0] + 1e-5f);
        float sh0 = beta[r0] + (bconv[r0] - mean[r0]) * inv0;
        float inv1 = gamma[r1] * rsqrtf(var[r1] + 1e-5f);
        float sh1 = beta[r1] + (bconv[r1] - mean[r1]) * inv1;
        float* base0 = g_attr + ((size_t)b * COUT + r0) * HW + nBase;
        float* base1 = g_attr + ((size_t)b * COUT + r1) * HW + nBase;
#pragma unroll
        for (int j = 0; j < 4; j++) {
            int col = warpN * 32 + j * 8 + 2 * lane4;
            float2 v0, v1;
            v0.x = fmaxf(acc[i][j][0] * inv0 + sh0, 0.f);
            v0.y = fmaxf(acc[i][j][1] * inv0 + sh0, 0.f);
            v1.x = fmaxf(acc[i][j][2] * inv1 + sh1, 0.f);
            v1.y = fmaxf(acc[i][j][3] * inv1 + sh1, 0.f);
            *(float2*)(base0 + col) = v0;
            *(float2*)(base1 + col) = v1;
        }
    }
}

// ---------------------------------------------------------------------------
// Kernel 3: copy boxes passthrough
// ---------------------------------------------------------------------------
__global__ void copy_boxes_kernel(const float* __restrict__ boxes, float* __restrict__ out) {
    int i = blockIdx.x * blockDim.x + threadIdx.x;
    if (i < BATCH * NROI * 4) out[i] = boxes[i];
}

// ---------------------------------------------------------------------------
// Kernel 4: ROI adaptive-avg-pool 5x5.
// grid(160, 16): block (br, 32-channel chunk). 8 warps x 4 channels each.
// Lane p*5+q computes one output bin.
// ---------------------------------------------------------------------------
__global__ void __launch_bounds__(256) roi_pool_kernel(const float* __restrict__ boxes,
                                                       float* __restrict__ out)
{
    const int br = blockIdx.x;           // 0..159
    const int chunk = blockIdx.y;        // 0..15
    const int b = br / NROI;
    const float* box = boxes + (size_t)br * 4;

    const float sx = (float)WW / 512.0f;
    const float sy = (float)HH / 512.0f;

    int x1 = min(max((int)floorf(box[0] * sx), 0), WW - 1);
    int y1 = min(max((int)floorf(box[1] * sy), 0), HH - 1);
    int x2 = min(max((int)ceilf(box[2] * sx), 0), WW - 1);
    int y2 = min(max((int)ceilf(box[3] * sy), 0), HH - 1);
    if (x2 <= x1) x2 = min(x1 + 1, WW);
    if (y2 <= y1) y2 = min(y1 + 1, HH);
    const int Lx = x2 - x1;
    const int Ly = y2 - y1;

    const int warp = threadIdx.x >> 5;
    const int lane = threadIdx.x & 31;

    int hs = 0, he = 0, ws = 0, we = 0;
    float invArea = 0.f;
    if (lane < 25) {
        int p = lane / 5, q = lane % 5;
        hs = y1 + (p * Ly) / 5;
        he = y1 + ((p + 1) * Ly + 4) / 5;
        ws = x1 + (q * Lx) / 5;
        we = x1 + ((q + 1) * Lx + 4) / 5;
        invArea = 1.0f / (float)((he - hs) * (we - ws));
    }

    const float* attrB = g_attr + (size_t)b * COUT * HW;
    float* outBR = out + (size_t)BATCH * NROI * 4 + (size_t)br * COUT * 25;

    for (int cc = warp; cc < 32; cc += 8) {
        int c = chunk * 32 + cc;
        if (lane < 25) {
            const float* plane = attrB + (size_t)c * HW;
            float s = 0.f;
            for (int h = hs; h < he; h++) {
                const float* row = plane + h * WW;
                for (int w = ws; w < we; w++) s += __ldg(row + w);
            }
            outBR[(size_t)c * 25 + lane] = s * invArea;
        }
    }
}

// ---------------------------------------------------------------------------
extern "C" void kernel_launch(void* const* d_in, const int* in_sizes, int n_in,
                              void* d_out, int out_size)
{
    const float* c3    = (const float*)d_in[0];
    const float* c4    = (const float*)d_in[1];
    const float* boxes = (const float*)d_in[2];
    const float* wconv = (const float*)d_in[3];
    const float* bconv = (const float*)d_in[4];
    const float* gamma = (const float*)d_in[5];
    const float* beta  = (const float*)d_in[6];
    const float* mean  = (const float*)d_in[7];
    const float* var   = (const float*)d_in[8];
    float* out = (float*)d_out;

    upsample_kernel<<<262144, 256>>>(c4);

    gemm_bn_relu_kernel<<<dim3(HW / BN, COUT / BM, BATCH), 256>>>(
        c3, wconv, bconv, gamma, beta, mean, var);

    copy_boxes_kernel<<<3, 256>>>(boxes, out);

    roi_pool_kernel<<<dim3(BATCH * NROI, 16), 256>>>(boxes, out);
}

// round 12
// speedup vs baseline: 3.7294x; 1.3509x over previous
#include <cuda_runtime.h>
#include <math.h>
#include <stdint.h>

#define BATCH 16
#define C3C 512
#define C4C 1024
#define CIN 1536
#define COUT 512
#define HH 64
#define WW 64
#define HW 4096
#define H4 32
#define NROI 10

#define TM 128
#define TN 128
#define BK 32
#define KIT (CIN / BK)      // 48
#define SMP 136             // smem row stride (floats): conflict-free + 16B multiple
#define STAGE_BYTES (2 * BK * SMP * 4)   // A + B per stage = 34816
#define NSTAGES 3
#define SMEM_TOTAL (NSTAGES * STAGE_BYTES + 16)

// Scratch (static device arrays — allocation-guard safe)
__device__ float g_c4u[(size_t)BATCH * C4C * HW];   // upsampled c4, tf32-pre-rounded
__device__ float g_c3r[(size_t)BATCH * C3C * HW];   // c3, tf32-pre-rounded
__device__ float g_attr[(size_t)BATCH * COUT * HW]; // conv+bn+relu output
__device__ float g_wt[(size_t)COUT * CIN];          // W, tf32, [mTile][k][m128] layout

__device__ __forceinline__ float f2tf32(float x) {
    unsigned u;
    asm("cvt.rna.tf32.f32 %0, %1;" : "=r"(u) : "f"(x));
    return __uint_as_float(u);
}
__device__ __forceinline__ uint32_t cvta_smem(const void* p) {
    uint32_t a;
    asm("{ .reg .u64 t; cvta.to.shared.u64 t, %1; cvt.u32.u64 %0, t; }" : "=r"(a) : "l"(p));
    return a;
}
__device__ __forceinline__ void cpasync16(uint32_t dst, const float* src) {
    asm volatile("cp.async.cg.shared.global [%0], [%1], 16;" :: "r"(dst), "l"(src) : "memory");
}
__device__ __forceinline__ void cp_commit() {
    asm volatile("cp.async.commit_group;" ::: "memory");
}

// ---------------------------------------------------------------------------
// Prep kernels
// ---------------------------------------------------------------------------
__global__ void __launch_bounds__(256) prep_w_kernel(const float* __restrict__ Wc) {
    int i = blockIdx.x * blockDim.x + threadIdx.x;      // 786432 total
    int mt = i / (CIN * 128);                            // FIX: CIN*128 not pow2
    int rem = i - mt * (CIN * 128);
    int k = rem >> 7;
    int m = rem & 127;
    g_wt[i] = f2tf32(Wc[(size_t)(mt * 128 + m) * CIN + k]);
}

__global__ void __launch_bounds__(256) round_c3_kernel(const float* __restrict__ c3) {
    size_t i = (size_t)blockIdx.x * blockDim.x + threadIdx.x;
    float4 v = *(const float4*)(c3 + i * 4);
    v.x = f2tf32(v.x); v.y = f2tf32(v.y); v.z = f2tf32(v.z); v.w = f2tf32(v.w);
    *(float4*)(g_c3r + i * 4) = v;
}

__global__ void __launch_bounds__(256) upsample_kernel(const float* __restrict__ c4) {
    size_t idx = (size_t)blockIdx.x * blockDim.x + threadIdx.x;
    int w = (int)(idx & 63);
    int h = (int)((idx >> 6) & 63);
    size_t bc = idx >> 12;
    const float* __restrict__ src = c4 + bc * (H4 * H4);

    float fy = h * 0.5f - 0.25f;
    int h0 = (int)floorf(fy);
    float ty = fy - (float)h0;
    int h1 = min(h0 + 1, H4 - 1);
    h0 = max(h0, 0);

    float fx = w * 0.5f - 0.25f;
    int w0 = (int)floorf(fx);
    float tx = fx - (float)w0;
    int w1 = min(w0 + 1, H4 - 1);
    w0 = max(w0, 0);

    float v00 = src[h0 * H4 + w0];
    float v01 = src[h0 * H4 + w1];
    float v10 = src[h1 * H4 + w0];
    float v11 = src[h1 * H4 + w1];
    float v = (1.f - ty) * ((1.f - tx) * v00 + tx * v01)
            +        ty  * ((1.f - tx) * v10 + tx * v11);
    g_c4u[idx] = f2tf32(v);
}

// ---------------------------------------------------------------------------
// GEMM: tf32 mma.sync, 128x128x32 tiles, 3-stage cp.async pipeline.
// A = g_wt (pre-transposed k-major), B = concat(g_c3r, g_c4u) rows (k-major).
// ---------------------------------------------------------------------------
__global__ void __launch_bounds__(256, 2) gemm_kernel(
    const float* __restrict__ bconv, const float* __restrict__ gamma,
    const float* __restrict__ beta, const float* __restrict__ mean,
    const float* __restrict__ var)
{
    extern __shared__ __align__(16) char dsm[];
    const uint32_t smem0 = cvta_smem(dsm);

    const int tid = threadIdx.x;
    const int lane = tid & 31;
    const int warpId = tid >> 5;
    const int warpM = warpId & 1;
    const int warpN = warpId >> 1;
    const int lane4 = lane & 3;
    const int laneq = lane >> 2;

    const int b = blockIdx.z;
    const int mTile = blockIdx.y;
    const int mBase = mTile * TM;
    const int nBase = blockIdx.x * TN;

    const float* __restrict__ At = g_wt + (size_t)mTile * CIN * 128;
    const float* __restrict__ c3b = g_c3r + (size_t)b * C3C * HW;
    const float* __restrict__ c4b = g_c4u + (size_t)b * C4C * HW;

    const int ck0 = tid >> 3;            // k row: 0..31
    const int cq0 = (tid & 7) * 4;       // float offset within row: 0..28

    auto issue_stage = [&](int i) {
        const int k0 = i * BK;
        const uint32_t sA = smem0 + (uint32_t)((i % NSTAGES) * STAGE_BYTES);
        const uint32_t sB = sA + (uint32_t)(BK * SMP * 4);
#pragma unroll
        for (int j = 0; j < 4; j++) {
            int q = cq0 + j * 32;
            cpasync16(sA + (uint32_t)((ck0 * SMP + q) * 4), At + (size_t)(k0 + ck0) * 128 + q);
        }
        {
            int c = k0 + ck0;
            const float* srow = (c < C3C) ? (c3b + (size_t)c * HW)
                                          : (c4b + (size_t)(c - C3C) * HW);
            srow += nBase;
#pragma unroll
            for (int j = 0; j < 4; j++) {
                int q = cq0 + j * 32;
                cpasync16(sB + (uint32_t)((ck0 * SMP + q) * 4), srow + q);
            }
        }
        cp_commit();
    };

    float acc[4][4][4];
#pragma unroll
    for (int i = 0; i < 4; i++)
#pragma unroll
        for (int j = 0; j < 4; j++)
#pragma unroll
            for (int r = 0; r < 4; r++) acc[i][j][r] = 0.f;

    issue_stage(0);
    issue_stage(1);

    for (int i = 0; i < KIT; i++) {
        if (i + 2 < KIT) {
            asm volatile("cp.async.wait_group 1;" ::: "memory");
        } else {
            asm volatile("cp.async.wait_group 0;" ::: "memory");
        }
        __syncthreads();
        if (i + 2 < KIT) issue_stage(i + 2);

        const float* As = (const float*)(dsm + (i % NSTAGES) * STAGE_BYTES);
        const float* Bs = As + BK * SMP;

#pragma unroll
        for (int ks = 0; ks < BK; ks += 8) {
            unsigned af[4][4];
#pragma unroll
            for (int ii = 0; ii < 4; ii++) {
                int m0 = warpM * 64 + ii * 16 + laneq;
                af[ii][0] = __float_as_uint(As[(ks + lane4) * SMP + m0]);
                af[ii][1] = __float_as_uint(As[(ks + lane4) * SMP + m0 + 8]);
                af[ii][2] = __float_as_uint(As[(ks + lane4 + 4) * SMP + m0]);
                af[ii][3] = __float_as_uint(As[(ks + lane4 + 4) * SMP + m0 + 8]);
            }
            unsigned bf[4][2];
#pragma unroll
            for (int jj = 0; jj < 4; jj++) {
                int n0 = warpN * 32 + jj * 8 + laneq;
                bf[jj][0] = __float_as_uint(Bs[(ks + lane4) * SMP + n0]);
                bf[jj][1] = __float_as_uint(Bs[(ks + lane4 + 4) * SMP + n0]);
            }
#pragma unroll
            for (int ii = 0; ii < 4; ii++)
#pragma unroll
                for (int jj = 0; jj < 4; jj++) {
                    asm volatile(
                        "mma.sync.aligned.m16n8k8.row.col.f32.tf32.tf32.f32 "
                        "{%0,%1,%2,%3}, {%4,%5,%6,%7}, {%8,%9}, {%0,%1,%2,%3};\n"
                        : "+f"(acc[ii][jj][0]), "+f"(acc[ii][jj][1]),
                          "+f"(acc[ii][jj][2]), "+f"(acc[ii][jj][3])
                        : "r"(af[ii][0]), "r"(af[ii][1]), "r"(af[ii][2]), "r"(af[ii][3]),
                          "r"(bf[jj][0]), "r"(bf[jj][1]));
                }
        }
        __syncthreads();
    }

    // epilogue: bias + BN + ReLU -> g_attr (register-based, proven mapping)
#pragma unroll
    for (int i = 0; i < 4; i++) {
        int r0 = mBase + warpM * 64 + i * 16 + laneq;
        int r1 = r0 + 8;
        float inv0 = gamma[r0] * rsqrtf(var[r0] + 1e-5f);
        float sh0 = beta[r0] + (bconv[r0] - mean[r0]) * inv0;
        float inv1 = gamma[r1] * rsqrtf(var[r1] + 1e-5f);
        float sh1 = beta[r1] + (bconv[r1] - mean[r1]) * inv1;
        float* base0 = g_attr + ((size_t)b * COUT + r0) * HW + nBase;
        float* base1 = g_attr + ((size_t)b * COUT + r1) * HW + nBase;
#pragma unroll
        for (int j = 0; j < 4; j++) {
            int col = warpN * 32 + j * 8 + 2 * lane4;
            float2 v0, v1;
            v0.x = fmaxf(acc[i][j][0] * inv0 + sh0, 0.f);
            v0.y = fmaxf(acc[i][j][1] * inv0 + sh0, 0.f);
            v1.x = fmaxf(acc[i][j][2] * inv1 + sh1, 0.f);
            v1.y = fmaxf(acc[i][j][3] * inv1 + sh1, 0.f);
            *(float2*)(base0 + col) = v0;
            *(float2*)(base1 + col) = v1;
        }
    }
}

// ---------------------------------------------------------------------------
__global__ void copy_boxes_kernel(const float* __restrict__ boxes, float* __restrict__ out) {
    int i = blockIdx.x * blockDim.x + threadIdx.x;
    if (i < BATCH * NROI * 4) out[i] = boxes[i];
}

// ---------------------------------------------------------------------------
// ROI adaptive-avg-pool 5x5. grid(160,16), block = 32-ch chunk.
// ---------------------------------------------------------------------------
__global__ void __launch_bounds__(256) roi_pool_kernel(const float* __restrict__ boxes,
                                                       float* __restrict__ out)
{
    const int br = blockIdx.x;
    const int chunk = blockIdx.y;
    const int b = br / NROI;
    const float* box = boxes + (size_t)br * 4;

    const float sx = (float)WW / 512.0f;
    const float sy = (float)HH / 512.0f;

    int x1 = min(max((int)floorf(box[0] * sx), 0), WW - 1);
    int y1 = min(max((int)floorf(box[1] * sy), 0), HH - 1);
    int x2 = min(max((int)ceilf(box[2] * sx), 0), WW - 1);
    int y2 = min(max((int)ceilf(box[3] * sy), 0), HH - 1);
    if (x2 <= x1) x2 = min(x1 + 1, WW);
    if (y2 <= y1) y2 = min(y1 + 1, HH);
    const int Lx = x2 - x1;
    const int Ly = y2 - y1;

    const int warp = threadIdx.x >> 5;
    const int lane = threadIdx.x & 31;

    int hs = 0, he = 0, ws = 0, we = 0;
    float invArea = 0.f;
    if (lane < 25) {
        int p = lane / 5, q = lane % 5;
        hs = y1 + (p * Ly) / 5;
        he = y1 + ((p + 1) * Ly + 4) / 5;
        ws = x1 + (q * Lx) / 5;
        we = x1 + ((q + 1) * Lx + 4) / 5;
        invArea = 1.0f / (float)((he - hs) * (we - ws));
    }

    const float* attrB = g_attr + (size_t)b * COUT * HW;
    float* outBR = out + (size_t)BATCH * NROI * 4 + (size_t)br * COUT * 25;

    for (int cc = warp; cc < 32; cc += 8) {
        int c = chunk * 32 + cc;
        if (lane < 25) {
            const float* plane = attrB + (size_t)c * HW;
            float s = 0.f;
            for (int h = hs; h < he; h++) {
                const float* row = plane + h * WW;
                for (int w = ws; w < we; w++) s += __ldg(row + w);
            }
            outBR[(size_t)c * 25 + lane] = s * invArea;
        }
    }
}

// ---------------------------------------------------------------------------
extern "C" void kernel_launch(void* const* d_in, const int* in_sizes, int n_in,
                              void* d_out, int out_size)
{
    const float* c3    = (const float*)d_in[0];
    const float* c4    = (const float*)d_in[1];
    const float* boxes = (const float*)d_in[2];
    const float* wconv = (const float*)d_in[3];
    const float* bconv = (const float*)d_in[4];
    const float* gamma = (const float*)d_in[5];
    const float* beta  = (const float*)d_in[6];
    const float* mean  = (const float*)d_in[7];
    const float* var   = (const float*)d_in[8];
    float* out = (float*)d_out;

    static int configured = 0;
    if (!configured) {
        cudaFuncSetAttribute(gemm_kernel,
                             cudaFuncAttributeMaxDynamicSharedMemorySize, SMEM_TOTAL);
        configured = 1;
    }

    prep_w_kernel<<<COUT * CIN / 256, 256>>>(wconv);
    round_c3_kernel<<<(size_t)BATCH * C3C * HW / 4 / 256, 256>>>(c3);
    upsample_kernel<<<262144, 256>>>(c4);

    gemm_kernel<<<dim3(HW / TN, COUT / TM, BATCH), 256, SMEM_TOTAL>>>(
        bconv, gamma, beta, mean, var);

    copy_boxes_kernel<<<3, 256>>>(boxes, out);

    roi_pool_kernel<<<dim3(BATCH * NROI, 16), 256>>>(boxes, out);
}

// round 13
// speedup vs baseline: 3.9974x; 1.0719x over previous
#include <cuda_runtime.h>
#include <math.h>
#include <stdint.h>

#define BATCH 16
#define C3C 512
#define C4C 1024
#define CIN 1536
#define COUT 512
#define HH 64
#define WW 64
#define HW 4096
#define H4 32
#define NROI 10

#define TM 128
#define TN 256
#define BK 32
#define KIT (CIN / BK)      // 48
#define SMPA 136            // A smem row stride (floats)
#define SMPB 264            // B smem row stride (floats); 264%32==8 -> conflict-free
#define A_STAGE (BK * SMPA * 4)          // 17408 B
#define B_STAGE (BK * SMPB * 4)          // 33792 B
#define STAGE_BYTES (A_STAGE + B_STAGE)  // 51200 B
#define NSTAGES 3
#define SMEM_TOTAL (NSTAGES * STAGE_BYTES + 16)   // 153616

// Scratch (static device arrays — allocation-guard safe)
__device__ float g_c4u[(size_t)BATCH * C4C * HW];   // upsampled c4, tf32-pre-rounded
__device__ float g_attr[(size_t)BATCH * COUT * HW]; // conv+bn+relu output
__device__ float g_wt[(size_t)COUT * CIN];          // W, tf32, [mTile][k][m128] layout

__device__ __forceinline__ float f2tf32(float x) {
    unsigned u;
    asm("cvt.rna.tf32.f32 %0, %1;" : "=r"(u) : "f"(x));
    return __uint_as_float(u);
}
__device__ __forceinline__ uint32_t cvta_smem(const void* p) {
    uint32_t a;
    asm("{ .reg .u64 t; cvta.to.shared.u64 t, %1; cvt.u32.u64 %0, t; }" : "=r"(a) : "l"(p));
    return a;
}
__device__ __forceinline__ void cpasync16(uint32_t dst, const float* src) {
    asm volatile("cp.async.cg.shared.global [%0], [%1], 16;" :: "r"(dst), "l"(src) : "memory");
}
__device__ __forceinline__ void cp_commit() {
    asm volatile("cp.async.commit_group;" ::: "memory");
}

// ---------------------------------------------------------------------------
// Prep kernels
// ---------------------------------------------------------------------------
__global__ void __launch_bounds__(256) prep_w_kernel(const float* __restrict__ Wc) {
    int i = blockIdx.x * blockDim.x + threadIdx.x;      // 786432 total
    int mt = i / (CIN * 128);
    int rem = i - mt * (CIN * 128);
    int k = rem >> 7;
    int m = rem & 127;
    g_wt[i] = f2tf32(Wc[(size_t)(mt * 128 + m) * CIN + k]);
}

__global__ void __launch_bounds__(256) upsample_kernel(const float* __restrict__ c4) {
    size_t idx = (size_t)blockIdx.x * blockDim.x + threadIdx.x;
    int w = (int)(idx & 63);
    int h = (int)((idx >> 6) & 63);
    size_t bc = idx >> 12;
    const float* __restrict__ src = c4 + bc * (H4 * H4);

    float fy = h * 0.5f - 0.25f;
    int h0 = (int)floorf(fy);
    float ty = fy - (float)h0;
    int h1 = min(h0 + 1, H4 - 1);
    h0 = max(h0, 0);

    float fx = w * 0.5f - 0.25f;
    int w0 = (int)floorf(fx);
    float tx = fx - (float)w0;
    int w1 = min(w0 + 1, H4 - 1);
    w0 = max(w0, 0);

    float v00 = src[h0 * H4 + w0];
    float v01 = src[h0 * H4 + w1];
    float v10 = src[h1 * H4 + w0];
    float v11 = src[h1 * H4 + w1];
    float v = (1.f - ty) * ((1.f - tx) * v00 + tx * v01)
            +        ty  * ((1.f - tx) * v10 + tx * v11);
    g_c4u[idx] = f2tf32(v);
}

// ---------------------------------------------------------------------------
// GEMM: tf32 mma.sync, CTA 128x256xBK32, warp tile 64x64, 3-stage cp.async.
// A = g_wt (pre-transposed k-major). B rows: raw c3 (k<512, HW-truncated tf32)
// or g_c4u (pre-rounded).
// ---------------------------------------------------------------------------
__global__ void __launch_bounds__(256, 1) gemm_kernel(
    const float* __restrict__ c3,
    const float* __restrict__ bconv, const float* __restrict__ gamma,
    const float* __restrict__ beta, const float* __restrict__ mean,
    const float* __restrict__ var)
{
    extern __shared__ __align__(16) char dsm[];
    const uint32_t smem0 = cvta_smem(dsm);

    const int tid = threadIdx.x;
    const int lane = tid & 31;
    const int warpId = tid >> 5;
    const int warpM = warpId & 1;    // 2 groups of 64 rows
    const int warpN = warpId >> 1;   // 4 groups of 64 cols
    const int lane4 = lane & 3;
    const int laneq = lane >> 2;

    const int b = blockIdx.z;
    const int mTile = blockIdx.y;
    const int mBase = mTile * TM;
    const int nBase = blockIdx.x * TN;

    const float* __restrict__ At = g_wt + (size_t)mTile * CIN * 128;
    const float* __restrict__ c3b = c3 + (size_t)b * C3C * HW;
    const float* __restrict__ c4b = g_c4u + (size_t)b * C4C * HW;

    const int ck0 = tid >> 3;            // k row: 0..31
    const int cq0 = (tid & 7) * 4;       // float offset within 32-col group

    auto issue_stage = [&](int i) {
        const int k0 = i * BK;
        const uint32_t sA = smem0 + (uint32_t)((i % NSTAGES) * STAGE_BYTES);
        const uint32_t sB = sA + (uint32_t)A_STAGE;
        const float* arow = At + (size_t)(k0 + ck0) * 128;
#pragma unroll
        for (int j = 0; j < 4; j++) {
            int q = cq0 + j * 32;
            cpasync16(sA + (uint32_t)((ck0 * SMPA + q) * 4), arow + q);
        }
        {
            int c = k0 + ck0;
            const float* srow = (c < C3C) ? (c3b + (size_t)c * HW)
                                          : (c4b + (size_t)(c - C3C) * HW);
            srow += nBase;
#pragma unroll
            for (int j = 0; j < 8; j++) {
                int q = cq0 + j * 32;
                cpasync16(sB + (uint32_t)((ck0 * SMPB + q) * 4), srow + q);
            }
        }
        cp_commit();
    };

    float acc[4][8][4];
#pragma unroll
    for (int i = 0; i < 4; i++)
#pragma unroll
        for (int j = 0; j < 8; j++)
#pragma unroll
            for (int r = 0; r < 4; r++) acc[i][j][r] = 0.f;

    issue_stage(0);
    issue_stage(1);

    for (int i = 0; i < KIT; i++) {
        if (i + 2 < KIT) {
            asm volatile("cp.async.wait_group 1;" ::: "memory");
        } else {
            asm volatile("cp.async.wait_group 0;" ::: "memory");
        }
        __syncthreads();
        if (i + 2 < KIT) issue_stage(i + 2);

        const float* As = (const float*)(dsm + (i % NSTAGES) * STAGE_BYTES);
        const float* Bs = (const float*)((const char*)As + A_STAGE);

#pragma unroll
        for (int ks = 0; ks < BK; ks += 8) {
            unsigned af[4][4];
#pragma unroll
            for (int ii = 0; ii < 4; ii++) {
                int m0 = warpM * 64 + ii * 16 + laneq;
                af[ii][0] = __float_as_uint(As[(ks + lane4) * SMPA + m0]);
                af[ii][1] = __float_as_uint(As[(ks + lane4) * SMPA + m0 + 8]);
                af[ii][2] = __float_as_uint(As[(ks + lane4 + 4) * SMPA + m0]);
                af[ii][3] = __float_as_uint(As[(ks + lane4 + 4) * SMPA + m0 + 8]);
            }
            unsigned bf[8][2];
#pragma unroll
            for (int jj = 0; jj < 8; jj++) {
                int n0 = warpN * 64 + jj * 8 + laneq;
                bf[jj][0] = __float_as_uint(Bs[(ks + lane4) * SMPB + n0]);
                bf[jj][1] = __float_as_uint(Bs[(ks + lane4 + 4) * SMPB + n0]);
            }
#pragma unroll
            for (int ii = 0; ii < 4; ii++)
#pragma unroll
                for (int jj = 0; jj < 8; jj++) {
                    asm volatile(
                        "mma.sync.aligned.m16n8k8.row.col.f32.tf32.tf32.f32 "
                        "{%0,%1,%2,%3}, {%4,%5,%6,%7}, {%8,%9}, {%0,%1,%2,%3};\n"
                        : "+f"(acc[ii][jj][0]), "+f"(acc[ii][jj][1]),
                          "+f"(acc[ii][jj][2]), "+f"(acc[ii][jj][3])
                        : "r"(af[ii][0]), "r"(af[ii][1]), "r"(af[ii][2]), "r"(af[ii][3]),
                          "r"(bf[jj][0]), "r"(bf[jj][1]));
                }
        }
        __syncthreads();
    }

    // epilogue: bias + BN + ReLU -> g_attr
#pragma unroll
    for (int i = 0; i < 4; i++) {
        int r0 = mBase + warpM * 64 + i * 16 + laneq;
        int r1 = r0 + 8;
        float inv0 = gamma[r0] * rsqrtf(var[r0] + 1e-5f);
        float sh0 = beta[r0] + (bconv[r0] - mean[r0]) * inv0;
        float inv1 = gamma[r1] * rsqrtf(var[r1] + 1e-5f);
        float sh1 = beta[r1] + (bconv[r1] - mean[r1]) * inv1;
        float* base0 = g_attr + ((size_t)b * COUT + r0) * HW + nBase;
        float* base1 = g_attr + ((size_t)b * COUT + r1) * HW + nBase;
#pragma unroll
        for (int j = 0; j < 8; j++) {
            int col = warpN * 64 + j * 8 + 2 * lane4;
            float2 v0, v1;
            v0.x = fmaxf(acc[i][j][0] * inv0 + sh0, 0.f);
            v0.y = fmaxf(acc[i][j][1] * inv0 + sh0, 0.f);
            v1.x = fmaxf(acc[i][j][2] * inv1 + sh1, 0.f);
            v1.y = fmaxf(acc[i][j][3] * inv1 + sh1, 0.f);
            *(float2*)(base0 + col) = v0;
            *(float2*)(base1 + col) = v1;
        }
    }
}

// ---------------------------------------------------------------------------
__global__ void copy_boxes_kernel(const float* __restrict__ boxes, float* __restrict__ out) {
    int i = blockIdx.x * blockDim.x + threadIdx.x;
    if (i < BATCH * NROI * 4) out[i] = boxes[i];
}

// ---------------------------------------------------------------------------
// ROI adaptive-avg-pool 5x5. grid(160,32), block = 16-ch chunk.
// ---------------------------------------------------------------------------
__global__ void __launch_bounds__(256) roi_pool_kernel(const float* __restrict__ boxes,
                                                       float* __restrict__ out)
{
    const int br = blockIdx.x;
    const int chunk = blockIdx.y;
    const int b = br / NROI;
    const float* box = boxes + (size_t)br * 4;

    const float sx = (float)WW / 512.0f;
    const float sy = (float)HH / 512.0f;

    int x1 = min(max((int)floorf(box[0] * sx), 0), WW - 1);
    int y1 = min(max((int)floorf(box[1] * sy), 0), HH - 1);
    int x2 = min(max((int)ceilf(box[2] * sx), 0), WW - 1);
    int y2 = min(max((int)ceilf(box[3] * sy), 0), HH - 1);
    if (x2 <= x1) x2 = min(x1 + 1, WW);
    if (y2 <= y1) y2 = min(y1 + 1, HH);
    const int Lx = x2 - x1;
    const int Ly = y2 - y1;

    const int warp = threadIdx.x >> 5;
    const int lane = threadIdx.x & 31;

    int hs = 0, he = 0, ws = 0, we = 0;
    float invArea = 0.f;
    if (lane < 25) {
        int p = lane / 5, q = lane % 5;
        hs = y1 + (p * Ly) / 5;
        he = y1 + ((p + 1) * Ly + 4) / 5;
        ws = x1 + (q * Lx) / 5;
        we = x1 + ((q + 1) * Lx + 4) / 5;
        invArea = 1.0f / (float)((he - hs) * (we - ws));
    }

    const float* attrB = g_attr + (size_t)b * COUT * HW;
    float* outBR = out + (size_t)BATCH * NROI * 4 + (size_t)br * COUT * 25;

    for (int cc = warp; cc < 16; cc += 8) {
        int c = chunk * 16 + cc;
        if (lane < 25) {
            const float* plane = attrB + (size_t)c * HW;
            float s = 0.f;
            for (int h = hs; h < he; h++) {
                const float* row = plane + h * WW;
                for (int w = ws; w < we; w++) s += __ldg(row + w);
            }
            outBR[(size_t)c * 25 + lane] = s * invArea;
        }
    }
}

// ---------------------------------------------------------------------------
extern "C" void kernel_launch(void* const* d_in, const int* in_sizes, int n_in,
                              void* d_out, int out_size)
{
    const float* c3    = (const float*)d_in[0];
    const float* c4    = (const float*)d_in[1];
    const float* boxes = (const float*)d_in[2];
    const float* wconv = (const float*)d_in[3];
    const float* bconv = (const float*)d_in[4];
    const float* gamma = (const float*)d_in[5];
    const float* beta  = (const float*)d_in[6];
    const float* mean  = (const float*)d_in[7];
    const float* var   = (const float*)d_in[8];
    float* out = (float*)d_out;

    static int configured = 0;
    if (!configured) {
        cudaFuncSetAttribute(gemm_kernel,
                             cudaFuncAttributeMaxDynamicSharedMemorySize, SMEM_TOTAL);
        configured = 1;
    }

    prep_w_kernel<<<COUT * CIN / 256, 256>>>(wconv);
    upsample_kernel<<<262144, 256>>>(c4);

    gemm_kernel<<<dim3(HW / TN, COUT / TM, BATCH), 256, SMEM_TOTAL>>>(
        c3, bconv, gamma, beta, mean, var);

    copy_boxes_kernel<<<3, 256>>>(boxes, out);

    roi_pool_kernel<<<dim3(BATCH * NROI, 32), 256>>>(boxes, out);
}

// round 14
// speedup vs baseline: 5.6435x; 1.4118x over previous
#include <cuda_runtime.h>
#include <cuda_fp16.h>
#include <math.h>
#include <stdint.h>

#define BATCH 16
#define C3C 512
#define C4C 1024
#define CIN 1536
#define COUT 512
#define HH 64
#define WW 64
#define HW 4096
#define H4 32
#define NROI 10

#define TM 128
#define TN 128
#define BK 32
#define KIT (CIN / BK)          // 48
#define AST 40                  // A smem stride (halves): 20 words -> conflict-free ldmatrix
#define BST 152                 // B smem stride (halves): 76 words -> conflict-free ldmatrix.trans
#define A_BYTES (TM * AST * 2)  // 10240
#define B_BYTES (BK * BST * 2)  // 9728
#define STAGE_BYTES (A_BYTES + B_BYTES)  // 19968
#define NSTAGES 3
#define SMEM_TOTAL (NSTAGES * STAGE_BYTES + 16)

// Scratch (static device arrays — allocation-guard safe)
__device__ __half g_wh[(size_t)COUT * CIN];           // W -> fp16, [o][k] (same layout)
__device__ __half g_c3h[(size_t)BATCH * C3C * HW];    // c3 -> fp16
__device__ __half g_c4uh[(size_t)BATCH * C4C * HW];   // upsampled c4 -> fp16
__device__ float g_attr[(size_t)BATCH * COUT * HW];   // conv+bn+relu output

__device__ __forceinline__ uint32_t cvta_smem(const void* p) {
    uint32_t a;
    asm("{ .reg .u64 t; cvta.to.shared.u64 t, %1; cvt.u32.u64 %0, t; }" : "=r"(a) : "l"(p));
    return a;
}
__device__ __forceinline__ void cpasync16(uint32_t dst, const void* src) {
    asm volatile("cp.async.cg.shared.global [%0], [%1], 16;" :: "r"(dst), "l"(src) : "memory");
}
__device__ __forceinline__ void cp_commit() {
    asm volatile("cp.async.commit_group;" ::: "memory");
}
__device__ __forceinline__ void ldsm4(uint32_t addr, unsigned& r0, unsigned& r1,
                                      unsigned& r2, unsigned& r3) {
    asm volatile("ldmatrix.sync.aligned.m8n8.x4.shared.b16 {%0,%1,%2,%3}, [%4];"
                 : "=r"(r0), "=r"(r1), "=r"(r2), "=r"(r3) : "r"(addr));
}
__device__ __forceinline__ void ldsm4t(uint32_t addr, unsigned& r0, unsigned& r1,
                                       unsigned& r2, unsigned& r3) {
    asm volatile("ldmatrix.sync.aligned.m8n8.x4.trans.shared.b16 {%0,%1,%2,%3}, [%4];"
                 : "=r"(r0), "=r"(r1), "=r"(r2), "=r"(r3) : "r"(addr));
}

// ---------------------------------------------------------------------------
// Prep kernels
// ---------------------------------------------------------------------------
__global__ void __launch_bounds__(256) prep_w_kernel(const float* __restrict__ Wc) {
    int i = blockIdx.x * blockDim.x + threadIdx.x;      // 786432 total
    g_wh[i] = __float2half_rn(Wc[i]);
}

__global__ void __launch_bounds__(256) prep_c3_kernel(const float* __restrict__ c3) {
    size_t i = (size_t)blockIdx.x * blockDim.x + threadIdx.x;
    float4 v = *(const float4*)(c3 + i * 4);
    __half2* o = (__half2*)(g_c3h + i * 4);
    o[0] = __floats2half2_rn(v.x, v.y);
    o[1] = __floats2half2_rn(v.z, v.w);
}

__global__ void __launch_bounds__(256) upsample_kernel(const float* __restrict__ c4) {
    size_t idx = (size_t)blockIdx.x * blockDim.x + threadIdx.x;
    int w = (int)(idx & 63);
    int h = (int)((idx >> 6) & 63);
    size_t bc = idx >> 12;
    const float* __restrict__ src = c4 + bc * (H4 * H4);

    float fy = h * 0.5f - 0.25f;
    int h0 = (int)floorf(fy);
    float ty = fy - (float)h0;
    int h1 = min(h0 + 1, H4 - 1);
    h0 = max(h0, 0);

    float fx = w * 0.5f - 0.25f;
    int w0 = (int)floorf(fx);
    float tx = fx - (float)w0;
    int w1 = min(w0 + 1, H4 - 1);
    w0 = max(w0, 0);

    float v00 = src[h0 * H4 + w0];
    float v01 = src[h0 * H4 + w1];
    float v10 = src[h1 * H4 + w0];
    float v11 = src[h1 * H4 + w1];
    float v = (1.f - ty) * ((1.f - tx) * v00 + tx * v01)
            +        ty  * ((1.f - tx) * v10 + tx * v11);
    g_c4uh[idx] = __float2half_rn(v);
}

// ---------------------------------------------------------------------------
// GEMM: fp16 mma.sync m16n8k16, CTA 128x128xBK32, warp tile 64x32,
// 3-stage cp.async pipeline, ldmatrix fragment loads.
// ---------------------------------------------------------------------------
__global__ void __launch_bounds__(256, 2) gemm_kernel(
    const float* __restrict__ bconv, const float* __restrict__ gamma,
    const float* __restrict__ beta, const float* __restrict__ mean,
    const float* __restrict__ var)
{
    extern __shared__ __align__(16) char dsm[];
    const uint32_t smem0 = cvta_smem(dsm);

    const int tid = threadIdx.x;
    const int lane = tid & 31;
    const int warpId = tid >> 5;
    const int warpM = warpId & 1;    // 2 groups of 64 rows
    const int warpN = warpId >> 1;   // 4 groups of 32 cols
    const int lane4 = lane & 3;
    const int laneq = lane >> 2;

    const int b = blockIdx.z;
    const int mBase = blockIdx.y * TM;
    const int nBase = blockIdx.x * TN;

    const __half* __restrict__ c3b = g_c3h + (size_t)b * C3C * HW;
    const __half* __restrict__ c4b = g_c4uh + (size_t)b * C4C * HW;

    // cp.async chunk mapping (2 chunks each for A and B per thread)
    // A: chunk = tid + 256j -> m = chunk>>2, cA = chunk&3 (4 chunks of 16B per 32-half row)
    // B: chunk = tid + 256j -> k = chunk>>4, cB = chunk&15 (16 chunks per 128-half row)
    auto issue_stage = [&](int i) {
        const int k0 = i * BK;
        const uint32_t sA = smem0 + (uint32_t)((i % NSTAGES) * STAGE_BYTES);
        const uint32_t sB = sA + (uint32_t)A_BYTES;
#pragma unroll
        for (int j = 0; j < 2; j++) {
            int chunk = tid + 256 * j;
            int m = chunk >> 2, cA = chunk & 3;
            cpasync16(sA + (uint32_t)(m * (AST * 2) + cA * 16),
                      g_wh + (size_t)(mBase + m) * CIN + k0 + cA * 8);
        }
#pragma unroll
        for (int j = 0; j < 2; j++) {
            int chunk = tid + 256 * j;
            int k = chunk >> 4, cB = chunk & 15;
            int ch = k0 + k;
            const __half* srow = (ch < C3C) ? (c3b + (size_t)ch * HW)
                                            : (c4b + (size_t)(ch - C3C) * HW);
            cpasync16(sB + (uint32_t)(k * (BST * 2) + cB * 16),
                      srow + nBase + cB * 8);
        }
        cp_commit();
    };

    // ldmatrix per-thread offsets (bytes)
    const uint32_t offA = (uint32_t)(((warpM * 64 + (lane & 15)) * AST + (lane >> 4) * 8) * 2);
    const uint32_t offB = (uint32_t)(((lane & 15) * BST + warpN * 32 + (lane >> 4) * 8) * 2);

    float acc[4][4][4];
#pragma unroll
    for (int i = 0; i < 4; i++)
#pragma unroll
        for (int j = 0; j < 4; j++)
#pragma unroll
            for (int r = 0; r < 4; r++) acc[i][j][r] = 0.f;

    issue_stage(0);
    issue_stage(1);

    for (int i = 0; i < KIT; i++) {
        if (i + 2 < KIT) {
            asm volatile("cp.async.wait_group 1;" ::: "memory");
        } else {
            asm volatile("cp.async.wait_group 0;" ::: "memory");
        }
        __syncthreads();
        if (i + 2 < KIT) issue_stage(i + 2);

        const uint32_t As = smem0 + (uint32_t)((i % NSTAGES) * STAGE_BYTES);
        const uint32_t Bs = As + (uint32_t)A_BYTES;

#pragma unroll
        for (int ks = 0; ks < BK; ks += 16) {
            unsigned af[4][4];
#pragma unroll
            for (int ii = 0; ii < 4; ii++)
                ldsm4(As + offA + (uint32_t)(ii * 16 * AST * 2 + ks * 2),
                      af[ii][0], af[ii][1], af[ii][2], af[ii][3]);
            unsigned bf[4][2];
#pragma unroll
            for (int J = 0; J < 2; J++) {
                unsigned r0, r1, r2, r3;
                ldsm4t(Bs + offB + (uint32_t)(ks * BST * 2 + J * 32), r0, r1, r2, r3);
                bf[2 * J][0] = r0; bf[2 * J][1] = r1;
                bf[2 * J + 1][0] = r2; bf[2 * J + 1][1] = r3;
            }
#pragma unroll
            for (int ii = 0; ii < 4; ii++)
#pragma unroll
                for (int jj = 0; jj < 4; jj++) {
                    asm volatile(
                        "mma.sync.aligned.m16n8k16.row.col.f32.f16.f16.f32 "
                        "{%0,%1,%2,%3}, {%4,%5,%6,%7}, {%8,%9}, {%0,%1,%2,%3};\n"
                        : "+f"(acc[ii][jj][0]), "+f"(acc[ii][jj][1]),
                          "+f"(acc[ii][jj][2]), "+f"(acc[ii][jj][3])
                        : "r"(af[ii][0]), "r"(af[ii][1]), "r"(af[ii][2]), "r"(af[ii][3]),
                          "r"(bf[jj][0]), "r"(bf[jj][1]));
                }
        }
        __syncthreads();
    }

    // epilogue: bias + BN + ReLU -> g_attr (proven mapping)
#pragma unroll
    for (int i = 0; i < 4; i++) {
        int r0 = mBase + warpM * 64 + i * 16 + laneq;
        int r1 = r0 + 8;
        float inv0 = gamma[r0] * rsqrtf(var[r0] + 1e-5f);
        float sh0 = beta[r0] + (bconv[r0] - mean[r0]) * inv0;
        float inv1 = gamma[r1] * rsqrtf(var[r1] + 1e-5f);
        float sh1 = beta[r1] + (bconv[r1] - mean[r1]) * inv1;
        float* base0 = g_attr + ((size_t)b * COUT + r0) * HW + nBase;
        float* base1 = g_attr + ((size_t)b * COUT + r1) * HW + nBase;
#pragma unroll
        for (int j = 0; j < 4; j++) {
            int col = warpN * 32 + j * 8 + 2 * lane4;
            float2 v0, v1;
            v0.x = fmaxf(acc[i][j][0] * inv0 + sh0, 0.f);
            v0.y = fmaxf(acc[i][j][1] * inv0 + sh0, 0.f);
            v1.x = fmaxf(acc[i][j][2] * inv1 + sh1, 0.f);
            v1.y = fmaxf(acc[i][j][3] * inv1 + sh1, 0.f);
            *(float2*)(base0 + col) = v0;
            *(float2*)(base1 + col) = v1;
        }
    }
}

// ---------------------------------------------------------------------------
__global__ void copy_boxes_kernel(const float* __restrict__ boxes, float* __restrict__ out) {
    int i = blockIdx.x * blockDim.x + threadIdx.x;
    if (i < BATCH * NROI * 4) out[i] = boxes[i];
}

// ---------------------------------------------------------------------------
// ROI adaptive-avg-pool 5x5. grid(160,32), block = 16-ch chunk.
// ---------------------------------------------------------------------------
__global__ void __launch_bounds__(256) roi_pool_kernel(const float* __restrict__ boxes,
                                                       float* __restrict__ out)
{
    const int br = blockIdx.x;
    const int chunk = blockIdx.y;
    const int b = br / NROI;
    const float* box = boxes + (size_t)br * 4;

    const float sx = (float)WW / 512.0f;
    const float sy = (float)HH / 512.0f;

    int x1 = min(max((int)floorf(box[0] * sx), 0), WW - 1);
    int y1 = min(max((int)floorf(box[1] * sy), 0), HH - 1);
    int x2 = min(max((int)ceilf(box[2] * sx), 0), WW - 1);
    int y2 = min(max((int)ceilf(box[3] * sy), 0), HH - 1);
    if (x2 <= x1) x2 = min(x1 + 1, WW);
    if (y2 <= y1) y2 = min(y1 + 1, HH);
    const int Lx = x2 - x1;
    const int Ly = y2 - y1;

    const int warp = threadIdx.x >> 5;
    const int lane = threadIdx.x & 31;

    int hs = 0, he = 0, ws = 0, we = 0;
    float invArea = 0.f;
    if (lane < 25) {
        int p = lane / 5, q = lane % 5;
        hs = y1 + (p * Ly) / 5;
        he = y1 + ((p + 1) * Ly + 4) / 5;
        ws = x1 + (q * Lx) / 5;
        we = x1 + ((q + 1) * Lx + 4) / 5;
        invArea = 1.0f / (float)((he - hs) * (we - ws));
    }

    const float* attrB = g_attr + (size_t)b * COUT * HW;
    float* outBR = out + (size_t)BATCH * NROI * 4 + (size_t)br * COUT * 25;

    for (int cc = warp; cc < 16; cc += 8) {
        int c = chunk * 16 + cc;
        if (lane < 25) {
            const float* plane = attrB + (size_t)c * HW;
            float s = 0.f;
            for (int h = hs; h < he; h++) {
                const float* row = plane + h * WW;
                for (int w = ws; w < we; w++) s += __ldg(row + w);
            }
            outBR[(size_t)c * 25 + lane] = s * invArea;
        }
    }
}

// ---------------------------------------------------------------------------
extern "C" void kernel_launch(void* const* d_in, const int* in_sizes, int n_in,
                              void* d_out, int out_size)
{
    const float* c3    = (const float*)d_in[0];
    const float* c4    = (const float*)d_in[1];
    const float* boxes = (const float*)d_in[2];
    const float* wconv = (const float*)d_in[3];
    const float* bconv = (const float*)d_in[4];
    const float* gamma = (const float*)d_in[5];
    const float* beta  = (const float*)d_in[6];
    const float* mean  = (const float*)d_in[7];
    const float* var   = (const float*)d_in[8];
    float* out = (float*)d_out;

    static int configured = 0;
    if (!configured) {
        cudaFuncSetAttribute(gemm_kernel,
                             cudaFuncAttributeMaxDynamicSharedMemorySize, SMEM_TOTAL);
        configured = 1;
    }

    prep_w_kernel<<<COUT * CIN / 256, 256>>>(wconv);
    prep_c3_kernel<<<(size_t)BATCH * C3C * HW / 4 / 256, 256>>>(c3);
    upsample_kernel<<<262144, 256>>>(c4);

    gemm_kernel<<<dim3(HW / TN, COUT / TM, BATCH), 256, SMEM_TOTAL>>>(
        bconv, gamma, beta, mean, var);

    copy_boxes_kernel<<<3, 256>>>(boxes, out);

    roi_pool_kernel<<<dim3(BATCH * NROI, 32), 256>>>(boxes, out);
}